// round 1
// baseline (speedup 1.0000x reference)
#include <cuda_runtime.h>

#define NDOC  128
#define NIN   625
#define NLEAF 4096
#define GEMM_KB 8      // K-split chunks for the GEMM (4096/8 = 512)
#define PAIR_SLOTS 10  // 8 leaf chunks (512 each) + 2 inner chunks (320/305)

// ---------------- scratch (device globals; no allocation) ----------------
__device__ float g_cs[8][NLEAF];          // partial column sums of exp(param)
__device__ float g_rs[NLEAF];             // 1 / colsum
__device__ float g_Wp[GEMM_KB][NIN * NDOC]; // split-K partials of W (node-major [j][d])
__device__ float g_z[NIN * NDOC];         // z, node-major [p][d]
__device__ float g_outp[PAIR_SLOTS][NDOC * NDOC]; // pairwise partials per K-chunk

__device__ __forceinline__ float tanh_apx(float x) {
    float y;
    asm("tanh.approx.f32 %0, %1;" : "=f"(y) : "f"(x));
    return y;
}

// -------- 1. partial column sums of exp(param) (param is [625][4096]) --------
__global__ __launch_bounds__(256) void k_colsum(const float* __restrict__ param) {
    int col = blockIdx.x * 256 + threadIdx.x;     // 16 blocks.x cover 4096 cols
    int rc  = blockIdx.y;                          // 8 row chunks of 79
    int r0 = rc * 79;
    int r1 = min(r0 + 79, NIN);
    float s = 0.f;
    for (int r = r0; r < r1; r++)
        s += __expf(param[r * NLEAF + col]);
    g_cs[rc][col] = s;
}

// -------- 2. combine partials, reciprocal --------
__global__ __launch_bounds__(256) void k_rs() {
    int col = blockIdx.x * 256 + threadIdx.x;
    float s = 0.f;
#pragma unroll
    for (int y = 0; y < 8; y++) s += g_cs[y][col];
    g_rs[col] = 1.0f / s;
}

// -------- 3. W = (mass * rs) @ exp(param).T  (M=128 docs, N=625 nodes, K=4096) --------
// grid: (20 node tiles of 32, 8 K chunks of 512); block 256.
// Thread computes a 4x4 micro-tile: docs {lane, lane+32, lane+64, lane+96} x nodes {jg*4..jg*4+3}.
__global__ __launch_bounds__(256) void k_gemm(const float* __restrict__ mass,
                                              const float* __restrict__ param) {
    __shared__ float sA[32 * 129];   // [k][doc], padded
    __shared__ float sB[32 * 33];    // [k][node], padded
    int j0 = blockIdx.x * 32;
    int kb = blockIdx.y;
    int l0 = kb * 512;
    int t = threadIdx.x;
    int lane = t & 31;
    int jg = t >> 5;

    float acc[4][4];
#pragma unroll
    for (int r = 0; r < 4; r++)
#pragma unroll
        for (int c = 0; c < 4; c++) acc[r][c] = 0.f;

    for (int kt = 0; kt < 16; kt++) {
        int lb = l0 + kt * 32;
        // load mass tile [128 docs][32 k] -> sA[k][doc], scaled by rs
#pragma unroll
        for (int i = 0; i < 16; i++) {
            int idx = t + i * 256;          // 0..4095
            int kk = idx & 31, d = idx >> 5;
            sA[kk * 129 + d] = mass[d * NLEAF + lb + kk] * g_rs[lb + kk];
        }
        // load exp(param) tile [32 nodes][32 k] -> sB[k][node]
#pragma unroll
        for (int i = 0; i < 4; i++) {
            int idx = t + i * 256;          // 0..1023
            int kk = idx & 31, jj = idx >> 5;
            int j = j0 + jj;
            sB[kk * 33 + jj] = (j < NIN) ? __expf(param[j * NLEAF + lb + kk]) : 0.f;
        }
        __syncthreads();
#pragma unroll
        for (int k = 0; k < 32; k++) {
            float a0 = sA[k * 129 + lane];
            float a1 = sA[k * 129 + lane + 32];
            float a2 = sA[k * 129 + lane + 64];
            float a3 = sA[k * 129 + lane + 96];
            float b0 = sB[k * 33 + jg * 4 + 0];
            float b1 = sB[k * 33 + jg * 4 + 1];
            float b2 = sB[k * 33 + jg * 4 + 2];
            float b3 = sB[k * 33 + jg * 4 + 3];
            acc[0][0] += a0 * b0; acc[0][1] += a0 * b1; acc[0][2] += a0 * b2; acc[0][3] += a0 * b3;
            acc[1][0] += a1 * b0; acc[1][1] += a1 * b1; acc[1][2] += a1 * b2; acc[1][3] += a1 * b3;
            acc[2][0] += a2 * b0; acc[2][1] += a2 * b1; acc[2][2] += a2 * b2; acc[2][3] += a2 * b3;
            acc[3][0] += a3 * b0; acc[3][1] += a3 * b1; acc[3][2] += a3 * b2; acc[3][3] += a3 * b3;
        }
        __syncthreads();
    }
#pragma unroll
    for (int c = 0; c < 4; c++) {
        int j = j0 + jg * 4 + c;
        if (j < NIN) {
#pragma unroll
            for (int r = 0; r < 4; r++)
                g_Wp[kb][j * NDOC + lane + 32 * r] = acc[r][c];
        }
    }
}

// -------- 4. deterministic combine of split-K partials --------
__global__ __launch_bounds__(256) void k_combine() {
    int idx = blockIdx.x * 256 + threadIdx.x;   // over p*128+d
    if (idx < NIN * NDOC) {
        float s = 0.f;
#pragma unroll
        for (int kb = 0; kb < GEMM_KB; kb++) s += g_Wp[kb][idx];
        g_z[idx] = s;
    }
}

// -------- 5. bottom-up subtree sums: z[p] += sum of children z --------
// children of p are 5p+1..min(5p+5, 624); iterating p descending keeps deps within one thread.
__global__ __launch_bounds__(128) void k_tree() {
    int d = threadIdx.x;   // one thread per doc; lanes coalesce over d
    for (int p = 124; p >= 0; p--) {
        float s = g_z[p * NDOC + d];
        int c0 = 5 * p + 1;
        int c1 = min(c0 + 5, NIN);
        for (int c = c0; c < c1; c++) s += g_z[c * NDOC + d];
        g_z[p * NDOC + d] = s;
    }
}

// -------- 6. pairwise smoothabs sums over both feature sets --------
// grid: (10 upper-tri 32x32 tile pairs, 10 K-chunk slots). slots 0..7: leaf (mass,
// doc-major, 512 K each). slots 8..9: inner (z, feature-major, 320 K each).
__constant__ int c_tpi[PAIR_SLOTS] = {0,0,0,0,1,1,1,2,2,3};
__constant__ int c_tpj[PAIR_SLOTS] = {0,1,2,3,1,2,3,2,3,3};

__global__ __launch_bounds__(256) void k_pair(const float* __restrict__ mass) {
    __shared__ float sI[32 * 33];   // [k][i-doc]
    __shared__ float sJ[32 * 33];   // [k][j-doc]
    int tp = blockIdx.x, s = blockIdx.y;
    int bi = c_tpi[tp], bj = c_tpj[tp];
    int i0 = bi * 32, j0 = bj * 32;
    int t = threadIdx.x;
    int tj  = t & 31;     // j-doc index (lane): coalesced direct output writes
    int tig = t >> 5;     // i-doc group: i in {tig, tig+8, tig+16, tig+24}

    bool feat = (s >= 8);
    const float* X;
    int k0, k1;
    if (feat) { X = g_z;  k0 = (s - 8) * 320; k1 = min(k0 + 320, NIN); }
    else      { X = mass; k0 = s * 512;       k1 = k0 + 512; }

    float acc0 = 0.f, acc1 = 0.f, acc2 = 0.f, acc3 = 0.f;

    for (int kt = k0; kt < k1; kt += 32) {
#pragma unroll
        for (int i = 0; i < 4; i++) {
            int idx = t + i * 256;            // 0..1023
            if (feat) {                       // z: [k][128] feature-major
                int ii = idx & 31, kk = idx >> 5;
                int kg = kt + kk;
                float vI = (kg < k1) ? X[kg * NDOC + i0 + ii] : 0.f;
                float vJ = (kg < k1) ? X[kg * NDOC + j0 + ii] : 0.f;
                sI[kk * 33 + ii] = vI;
                sJ[kk * 33 + ii] = vJ;
            } else {                          // mass: [128][4096] doc-major
                int kk = idx & 31, ii = idx >> 5;
                int kg = kt + kk;
                float vI = (kg < k1) ? X[(i0 + ii) * NLEAF + kg] : 0.f;
                float vJ = (kg < k1) ? X[(j0 + ii) * NLEAF + kg] : 0.f;
                sI[kk * 33 + ii] = vI;
                sJ[kk * 33 + ii] = vJ;
            }
        }
        __syncthreads();
#pragma unroll
        for (int k = 0; k < 32; k++) {
            float b  = sJ[k * 33 + tj];           // lane-consecutive, conflict-free
            float a0 = sI[k * 33 + tig];          // broadcast within warp
            float a1 = sI[k * 33 + tig + 8];
            float a2 = sI[k * 33 + tig + 16];
            float a3 = sI[k * 33 + tig + 24];
            float d0 = a0 - b, d1 = a1 - b, d2 = a2 - b, d3 = a3 - b;
            acc0 += d0 * tanh_apx(d0);            // smoothabs(x,2) == x*tanh(x)
            acc1 += d1 * tanh_apx(d1);
            acc2 += d2 * tanh_apx(d2);
            acc3 += d3 * tanh_apx(d3);
        }
        __syncthreads();
    }

    float* op = g_outp[s];
    int j = j0 + tj;
    int i;
    i = i0 + tig;      op[i * NDOC + j] = acc0; if (bi != bj) op[j * NDOC + i] = acc0;
    i = i0 + tig + 8;  op[i * NDOC + j] = acc1; if (bi != bj) op[j * NDOC + i] = acc1;
    i = i0 + tig + 16; op[i * NDOC + j] = acc2; if (bi != bj) op[j * NDOC + i] = acc2;
    i = i0 + tig + 24; op[i * NDOC + j] = acc3; if (bi != bj) op[j * NDOC + i] = acc3;
}

// -------- 7. deterministic final reduce over the 10 slots --------
__global__ __launch_bounds__(256) void k_reduce(float* __restrict__ out) {
    int idx = blockIdx.x * 256 + threadIdx.x;    // 64 blocks * 256 = 16384 exact
    float s = 0.f;
#pragma unroll
    for (int t = 0; t < PAIR_SLOTS; t++) s += g_outp[t][idx];
    out[idx] = s;
}

// ---------------- launch ----------------
extern "C" void kernel_launch(void* const* d_in, const int* in_sizes, int n_in,
                              void* d_out, int out_size) {
    const float* mass  = (const float*)d_in[0];   // (128, 4096)
    const float* param = (const float*)d_in[1];   // (625, 4096)
    // robustness: identify by size in case metadata order differs
    if (n_in >= 2 && in_sizes[0] == NIN * NLEAF && in_sizes[1] == NDOC * NLEAF) {
        param = (const float*)d_in[0];
        mass  = (const float*)d_in[1];
    }
    float* out = (float*)d_out;

    k_colsum<<<dim3(16, 8), 256>>>(param);
    k_rs<<<16, 256>>>();
    k_gemm<<<dim3(20, GEMM_KB), 256>>>(mass, param);
    k_combine<<<(NIN * NDOC + 255) / 256, 256>>>();
    k_tree<<<1, 128>>>();
    k_pair<<<dim3(10, PAIR_SLOTS), 256>>>(mass);
    k_reduce<<<64, 256>>>(out);
}

// round 3
// speedup vs baseline: 2.3833x; 2.3833x over previous
#include <cuda_runtime.h>

#define NDOC  128
#define NIN   625
#define NLEAF 4096
#define GEMM_KB 14     // K-split chunks: 280 blocks = 2 waves of 140, <=2/SM co-resident
#define PAIR_SLOTS 14  // 10 leaf K-chunks + 4 inner K-chunks

// ---------------- scratch (device globals; no allocation) ----------------
__device__ float g_cs[8][NLEAF];                  // partial column sums of exp(param)
__device__ float g_rs[NLEAF];                     // 1 / colsum
__device__ float g_Wp[GEMM_KB][NIN * NDOC];       // split-K partials of W (node-major [j][d])
__device__ float g_z[NIN * NDOC];                 // z, node-major [p][d]
__device__ float g_outp[PAIR_SLOTS][NDOC * NDOC]; // pairwise partials per K-chunk

__device__ __forceinline__ float tanh_apx(float x) {
    float y;
    asm("tanh.approx.f32 %0, %1;" : "=f"(y) : "f"(x));
    return y;
}

// -------- 1. partial column sums of exp(param) (param is [625][4096]) --------
__global__ __launch_bounds__(256) void k_colsum(const float* __restrict__ param) {
    int col = blockIdx.x * 256 + threadIdx.x;     // 16 blocks.x cover 4096 cols
    int rc  = blockIdx.y;                          // 8 row chunks of 79
    int r0 = rc * 79;
    int r1 = min(r0 + 79, NIN);
    float s = 0.f;
    for (int r = r0; r < r1; r++)
        s += __expf(param[r * NLEAF + col]);
    g_cs[rc][col] = s;
}

// -------- 2. combine partials, reciprocal --------
__global__ __launch_bounds__(256) void k_rs() {
    int col = blockIdx.x * 256 + threadIdx.x;
    float s = 0.f;
#pragma unroll
    for (int y = 0; y < 8; y++) s += g_cs[y][col];
    g_rs[col] = 1.0f / s;
}

// -------- 3. W = (mass * rs) @ exp(param).T  (M=128 docs, N=625 nodes, K=4096) --------
// grid: (20 node tiles of 32, 14 K chunks); block 256, 2 blocks/SM co-resident.
// K chunks in units of 32-wide k-tiles: 128 tiles total; chunks 0,1 get 10 tiles, rest 9.
__global__ __launch_bounds__(256, 2) void k_gemm(const float* __restrict__ mass,
                                                 const float* __restrict__ param) {
    __shared__ float sA[32 * 129];   // [k][doc], padded
    __shared__ float sB[32 * 33];    // [k][node], padded
    int j0 = blockIdx.x * 32;
    int kb = blockIdx.y;
    int t0 = kb * 9 + min(kb, 2);            // first k-tile of this chunk
    int nt = 9 + (kb < 2 ? 1 : 0);           // tiles in this chunk
    int t = threadIdx.x;
    int lane = t & 31;
    int jg = t >> 5;

    float acc[4][4];
#pragma unroll
    for (int r = 0; r < 4; r++)
#pragma unroll
        for (int c = 0; c < 4; c++) acc[r][c] = 0.f;

    for (int kt = 0; kt < nt; kt++) {
        int lb = (t0 + kt) * 32;
        // load mass tile [128 docs][32 k] -> sA[k][doc], scaled by rs
#pragma unroll
        for (int i = 0; i < 16; i++) {
            int idx = t + i * 256;          // 0..4095
            int kk = idx & 31, d = idx >> 5;
            sA[kk * 129 + d] = mass[d * NLEAF + lb + kk] * g_rs[lb + kk];
        }
        // load exp(param) tile [32 nodes][32 k] -> sB[k][node]
#pragma unroll
        for (int i = 0; i < 4; i++) {
            int idx = t + i * 256;          // 0..1023
            int kk = idx & 31, jj = idx >> 5;
            int j = j0 + jj;
            sB[kk * 33 + jj] = (j < NIN) ? __expf(param[j * NLEAF + lb + kk]) : 0.f;
        }
        __syncthreads();
#pragma unroll
        for (int k = 0; k < 32; k++) {
            float a0 = sA[k * 129 + lane];
            float a1 = sA[k * 129 + lane + 32];
            float a2 = sA[k * 129 + lane + 64];
            float a3 = sA[k * 129 + lane + 96];
            float b0 = sB[k * 33 + jg * 4 + 0];
            float b1 = sB[k * 33 + jg * 4 + 1];
            float b2 = sB[k * 33 + jg * 4 + 2];
            float b3 = sB[k * 33 + jg * 4 + 3];
            acc[0][0] += a0 * b0; acc[0][1] += a0 * b1; acc[0][2] += a0 * b2; acc[0][3] += a0 * b3;
            acc[1][0] += a1 * b0; acc[1][1] += a1 * b1; acc[1][2] += a1 * b2; acc[1][3] += a1 * b3;
            acc[2][0] += a2 * b0; acc[2][1] += a2 * b1; acc[2][2] += a2 * b2; acc[2][3] += a2 * b3;
            acc[3][0] += a3 * b0; acc[3][1] += a3 * b1; acc[3][2] += a3 * b2; acc[3][3] += a3 * b3;
        }
        __syncthreads();
    }
#pragma unroll
    for (int c = 0; c < 4; c++) {
        int j = j0 + jg * 4 + c;
        if (j < NIN) {
#pragma unroll
            for (int r = 0; r < 4; r++)
                g_Wp[kb][j * NDOC + lane + 32 * r] = acc[r][c];
        }
    }
}

// -------- 4. deterministic combine of split-K partials (float4) --------
__global__ __launch_bounds__(256) void k_combine() {
    int idx = blockIdx.x * 256 + threadIdx.x;   // over 20000 float4
    if (idx < NIN * NDOC / 4) {
        float4 s = make_float4(0.f, 0.f, 0.f, 0.f);
#pragma unroll
        for (int kb = 0; kb < GEMM_KB; kb++) {
            float4 v = ((const float4*)g_Wp[kb])[idx];
            s.x += v.x; s.y += v.y; s.z += v.z; s.w += v.w;
        }
        ((float4*)g_z)[idx] = s;
    }
}

// -------- 5. bottom-up subtree sums, level-parallel (one block, 4 phases) --------
// parents with children: 0..124. Levels bottom-up: {31..124}, {6..30}, {1..5}, {0}.
__global__ __launch_bounds__(1024) void k_tree() {
    int t = threadIdx.x;
    // phase 1: parents 31..124 (children 156..624, childless)
    for (int i = t; i < 94 * NDOC; i += 1024) {
        int p = 31 + (i >> 7), d = i & 127;
        float s = g_z[p * NDOC + d];
        int c0 = 5 * p + 1, c1 = min(c0 + 5, NIN);
        for (int c = c0; c < c1; c++) s += g_z[c * NDOC + d];
        g_z[p * NDOC + d] = s;
    }
    __syncthreads();
    // phase 2: parents 6..30
    for (int i = t; i < 25 * NDOC; i += 1024) {
        int p = 6 + (i >> 7), d = i & 127;
        float s = g_z[p * NDOC + d];
        int c0 = 5 * p + 1;
        for (int c = c0; c < c0 + 5; c++) s += g_z[c * NDOC + d];
        g_z[p * NDOC + d] = s;
    }
    __syncthreads();
    // phase 3: parents 1..5
    for (int i = t; i < 5 * NDOC; i += 1024) {
        int p = 1 + (i >> 7), d = i & 127;
        float s = g_z[p * NDOC + d];
        int c0 = 5 * p + 1;
        for (int c = c0; c < c0 + 5; c++) s += g_z[c * NDOC + d];
        g_z[p * NDOC + d] = s;
    }
    __syncthreads();
    // phase 4: root
    if (t < NDOC) {
        int d = t;
        float s = g_z[d];
        for (int c = 1; c <= 5; c++) s += g_z[c * NDOC + d];
        g_z[d] = s;
    }
}

// -------- 6. pairwise smoothabs sums --------
// grid: (10 upper-tri 32x32 tile pairs, 14 K-slots).
// slots 0..9: leaf (mass, doc-major); K in 32-wide tiles: slots 0..7 get 13 tiles, 8..9 get 12.
//   leaf uses smoothabs(x,2) ~= x*x (|x| <= ~1e-3, error <= x^4/3 ~ 3e-13/term).
// slots 10..13: inner (z, feature-major), 160 K each (last 145); uses x*tanh(x).
__constant__ int c_tpi[10] = {0,0,0,0,1,1,1,2,2,3};
__constant__ int c_tpj[10] = {0,1,2,3,1,2,3,2,3,3};

__global__ __launch_bounds__(256) void k_pair(const float* __restrict__ mass) {
    __shared__ float sI[32 * 33];   // [k][i-doc]
    __shared__ float sJ[32 * 33];   // [k][j-doc]
    int tp = blockIdx.x, s = blockIdx.y;
    int bi = c_tpi[tp], bj = c_tpj[tp];
    int i0 = bi * 32, j0 = bj * 32;
    int t = threadIdx.x;
    int tj  = t & 31;     // j-doc lane
    int tig = t >> 5;     // i in {tig, tig+8, tig+16, tig+24}

    float acc0 = 0.f, acc1 = 0.f, acc2 = 0.f, acc3 = 0.f;

    if (s < 10) {
        // ---- leaf part: mass doc-major, quadratic smoothabs ----
        int t0 = (s < 8) ? s * 13 : 104 + (s - 8) * 12;
        int nt = (s < 8) ? 13 : 12;
        for (int kt = 0; kt < nt; kt++) {
            int kb = (t0 + kt) * 32;
#pragma unroll
            for (int i = 0; i < 4; i++) {
                int idx = t + i * 256;            // 0..1023
                int kk = idx & 31, ii = idx >> 5;
                int kg = kb + kk;
                sI[kk * 33 + ii] = mass[(i0 + ii) * NLEAF + kg];
                sJ[kk * 33 + ii] = mass[(j0 + ii) * NLEAF + kg];
            }
            __syncthreads();
#pragma unroll
            for (int k = 0; k < 32; k++) {
                float b  = sJ[k * 33 + tj];
                float d0 = sI[k * 33 + tig]      - b;
                float d1 = sI[k * 33 + tig + 8]  - b;
                float d2 = sI[k * 33 + tig + 16] - b;
                float d3 = sI[k * 33 + tig + 24] - b;
                acc0 += d0 * d0;
                acc1 += d1 * d1;
                acc2 += d2 * d2;
                acc3 += d3 * d3;
            }
            __syncthreads();
        }
    } else {
        // ---- inner part: z feature-major, x*tanh(x) ----
        int k0 = (s - 10) * 160;
        int k1 = min(k0 + 160, NIN);
        for (int kt = k0; kt < k1; kt += 32) {
#pragma unroll
            for (int i = 0; i < 4; i++) {
                int idx = t + i * 256;            // 0..1023
                int ii = idx & 31, kk = idx >> 5;
                int kg = kt + kk;
                float vI = (kg < k1) ? g_z[kg * NDOC + i0 + ii] : 0.f;
                float vJ = (kg < k1) ? g_z[kg * NDOC + j0 + ii] : 0.f;
                sI[kk * 33 + ii] = vI;
                sJ[kk * 33 + ii] = vJ;
            }
            __syncthreads();
#pragma unroll
            for (int k = 0; k < 32; k++) {
                float b  = sJ[k * 33 + tj];
                float d0 = sI[k * 33 + tig]      - b;
                float d1 = sI[k * 33 + tig + 8]  - b;
                float d2 = sI[k * 33 + tig + 16] - b;
                float d3 = sI[k * 33 + tig + 24] - b;
                acc0 += d0 * tanh_apx(d0);
                acc1 += d1 * tanh_apx(d1);
                acc2 += d2 * tanh_apx(d2);
                acc3 += d3 * tanh_apx(d3);
            }
            __syncthreads();
        }
    }

    float* op = g_outp[s];
    int j = j0 + tj;
    int i;
    i = i0 + tig;      op[i * NDOC + j] = acc0; if (bi != bj) op[j * NDOC + i] = acc0;
    i = i0 + tig + 8;  op[i * NDOC + j] = acc1; if (bi != bj) op[j * NDOC + i] = acc1;
    i = i0 + tig + 16; op[i * NDOC + j] = acc2; if (bi != bj) op[j * NDOC + i] = acc2;
    i = i0 + tig + 24; op[i * NDOC + j] = acc3; if (bi != bj) op[j * NDOC + i] = acc3;
}

// -------- 7. deterministic final reduce over the 14 slots (float4) --------
__global__ __launch_bounds__(256) void k_reduce(float* __restrict__ out) {
    int idx = blockIdx.x * 256 + threadIdx.x;    // 16 blocks * 256 = 4096 float4 exact
    float4 s = make_float4(0.f, 0.f, 0.f, 0.f);
#pragma unroll
    for (int t = 0; t < PAIR_SLOTS; t++) {
        float4 v = ((const float4*)g_outp[t])[idx];
        s.x += v.x; s.y += v.y; s.z += v.z; s.w += v.w;
    }
    ((float4*)out)[idx] = s;
}

// ---------------- launch ----------------
extern "C" void kernel_launch(void* const* d_in, const int* in_sizes, int n_in,
                              void* d_out, int out_size) {
    const float* mass  = (const float*)d_in[0];   // (128, 4096)
    const float* param = (const float*)d_in[1];   // (625, 4096)
    if (n_in >= 2 && in_sizes[0] == NIN * NLEAF && in_sizes[1] == NDOC * NLEAF) {
        param = (const float*)d_in[0];
        mass  = (const float*)d_in[1];
    }
    float* out = (float*)d_out;

    k_colsum<<<dim3(16, 8), 256>>>(param);
    k_rs<<<16, 256>>>();
    k_gemm<<<dim3(20, GEMM_KB), 256>>>(mass, param);
    k_combine<<<(NIN * NDOC / 4 + 255) / 256, 256>>>();
    k_tree<<<1, 1024>>>();
    k_pair<<<dim3(10, PAIR_SLOTS), 256>>>(mass);
    k_reduce<<<16, 256>>>(out);
}

// round 4
// speedup vs baseline: 2.5310x; 1.0620x over previous
#include <cuda_runtime.h>

#define NDOC  128
#define NIN   625
#define NLEAF 4096
#define GEMM_KB 14     // main gemm K-split: 280 blocks, 2/SM co-resident
#define GKB    28      // leaf-G gemm K-split: 280 blocks of 64 threads
#define INNER_SLOTS 16 // inner pairwise K-slots (40 features each)

// ---------------- scratch (device globals; no allocation) ----------------
__device__ __align__(16) float g_cs[8][NLEAF];
__device__ __align__(16) float g_rs[NLEAF];
__device__ __align__(16) float g_Wp[GEMM_KB][NIN * NDOC];   // split-K partials of W
__device__ __align__(16) float g_z[NIN * NDOC];             // z, node-major [p][d]
__device__ __align__(16) float g_outp[INNER_SLOTS][NDOC * NDOC]; // inner pairwise partials
__device__ __align__(16) float g_Gp[GKB][NDOC * NDOC];      // mass@mass.T partials
__device__ __align__(16) float g_n[NDOC];                   // row norms of mass

__device__ __forceinline__ float tanh_apx(float x) {
    float y;
    asm("tanh.approx.f32 %0, %1;" : "=f"(y) : "f"(x));
    return y;
}

// -------- 1. partial column sums of exp(param) --------
__global__ __launch_bounds__(256) void k_colsum(const float* __restrict__ param) {
    int col = blockIdx.x * 256 + threadIdx.x;
    int rc  = blockIdx.y;
    int r0 = rc * 79;
    int r1 = min(r0 + 79, NIN);
    float s = 0.f;
    for (int r = r0; r < r1; r++)
        s += __expf(param[r * NLEAF + col]);
    g_cs[rc][col] = s;
}

// -------- 2. combine partials, reciprocal --------
__global__ __launch_bounds__(256) void k_rs() {
    int col = blockIdx.x * 256 + threadIdx.x;
    float s = 0.f;
#pragma unroll
    for (int y = 0; y < 8; y++) s += g_cs[y][col];
    g_rs[col] = 1.0f / s;
}

// -------- 3. W = (mass * rs) @ exp(param).T, vectorized 4x4 micro-tile --------
// thread owns docs 4*lane..+3 (consecutive) x nodes jg*4..+3 (consecutive).
__global__ __launch_bounds__(256, 2) void k_gemm(const float* __restrict__ mass,
                                                 const float* __restrict__ param) {
    __shared__ __align__(16) float sA[32 * 132];   // [k][doc], stride 132 (16B-aligned rows)
    __shared__ __align__(16) float sB[32 * 36];    // [k][node], stride 36
    int j0 = blockIdx.x * 32;
    int kb = blockIdx.y;
    int t0 = kb * 9 + min(kb, 2);
    int nt = 9 + (kb < 2 ? 1 : 0);
    int t = threadIdx.x;
    int lane = t & 31;
    int jg = t >> 5;

    float acc[4][4];
#pragma unroll
    for (int r = 0; r < 4; r++)
#pragma unroll
        for (int c = 0; c < 4; c++) acc[r][c] = 0.f;

    for (int kt = 0; kt < nt; kt++) {
        int lb = (t0 + kt) * 32;
#pragma unroll
        for (int i = 0; i < 16; i++) {
            int idx = t + i * 256;
            int kk = idx & 31, d = idx >> 5;
            sA[kk * 132 + d] = mass[d * NLEAF + lb + kk] * g_rs[lb + kk];
        }
#pragma unroll
        for (int i = 0; i < 4; i++) {
            int idx = t + i * 256;
            int kk = idx & 31, jj = idx >> 5;
            int j = j0 + jj;
            sB[kk * 36 + jj] = (j < NIN) ? __expf(param[j * NLEAF + lb + kk]) : 0.f;
        }
        __syncthreads();
#pragma unroll
        for (int k = 0; k < 32; k++) {
            float4 a = *(const float4*)&sA[k * 132 + 4 * lane];
            float4 b = *(const float4*)&sB[k * 36 + jg * 4];
            acc[0][0] += a.x * b.x; acc[0][1] += a.x * b.y; acc[0][2] += a.x * b.z; acc[0][3] += a.x * b.w;
            acc[1][0] += a.y * b.x; acc[1][1] += a.y * b.y; acc[1][2] += a.y * b.z; acc[1][3] += a.y * b.w;
            acc[2][0] += a.z * b.x; acc[2][1] += a.z * b.y; acc[2][2] += a.z * b.z; acc[2][3] += a.z * b.w;
            acc[3][0] += a.w * b.x; acc[3][1] += a.w * b.y; acc[3][2] += a.w * b.z; acc[3][3] += a.w * b.w;
        }
        __syncthreads();
    }
#pragma unroll
    for (int c = 0; c < 4; c++) {
        int j = j0 + jg * 4 + c;
        if (j < NIN)
            *(float4*)&g_Wp[kb][j * NDOC + 4 * lane] =
                make_float4(acc[0][c], acc[1][c], acc[2][c], acc[3][c]);
    }
}

// -------- 4. combine split-K partials (scalar: 80000 threads for latency hiding) --------
__global__ __launch_bounds__(256) void k_combine() {
    int idx = blockIdx.x * 256 + threadIdx.x;
    if (idx < NIN * NDOC) {
        float s = 0.f;
#pragma unroll
        for (int kb = 0; kb < GEMM_KB; kb++) s += g_Wp[kb][idx];
        g_z[idx] = s;
    }
}

// -------- 5. bottom-up subtree sums, level-parallel, float4 --------
__global__ __launch_bounds__(1024) void k_tree() {
    float4* z4 = (float4*)g_z;   // 32 float4 per node row
    int t = threadIdx.x;
    // phase 1: parents 31..124
    for (int i = t; i < 94 * 32; i += 1024) {
        int p = 31 + (i >> 5), q = i & 31;
        float4 s = z4[p * 32 + q];
        int c0 = 5 * p + 1, c1 = min(c0 + 5, NIN);
        for (int c = c0; c < c1; c++) {
            float4 v = z4[c * 32 + q];
            s.x += v.x; s.y += v.y; s.z += v.z; s.w += v.w;
        }
        z4[p * 32 + q] = s;
    }
    __syncthreads();
    // phase 2: parents 6..30
    for (int i = t; i < 25 * 32; i += 1024) {
        int p = 6 + (i >> 5), q = i & 31;
        float4 s = z4[p * 32 + q];
        int c0 = 5 * p + 1;
        for (int c = c0; c < c0 + 5; c++) {
            float4 v = z4[c * 32 + q];
            s.x += v.x; s.y += v.y; s.z += v.z; s.w += v.w;
        }
        z4[p * 32 + q] = s;
    }
    __syncthreads();
    // phase 3: parents 1..5
    if (t < 5 * 32) {
        int p = 1 + (t >> 5), q = t & 31;
        float4 s = z4[p * 32 + q];
        int c0 = 5 * p + 1;
        for (int c = c0; c < c0 + 5; c++) {
            float4 v = z4[c * 32 + q];
            s.x += v.x; s.y += v.y; s.z += v.z; s.w += v.w;
        }
        z4[p * 32 + q] = s;
    }
    __syncthreads();
    // phase 4: root
    if (t < 32) {
        float4 s = z4[t];
        for (int c = 1; c <= 5; c++) {
            float4 v = z4[c * 32 + t];
            s.x += v.x; s.y += v.y; s.z += v.z; s.w += v.w;
        }
        z4[t] = s;
    }
}

// -------- 6a. row norms of mass: n[d] = sum_k mass[d,k]^2 --------
__global__ __launch_bounds__(256) void k_norm(const float* __restrict__ mass) {
    int w = threadIdx.x >> 5, lane = threadIdx.x & 31;
    int d = blockIdx.x * 8 + w;
    float s = 0.f;
    for (int k = lane; k < NLEAF; k += 32) {
        float v = mass[d * NLEAF + k];
        s += v * v;
    }
#pragma unroll
    for (int o = 16; o > 0; o >>= 1) s += __shfl_xor_sync(0xffffffffu, s, o);
    if (lane == 0) g_n[d] = s;
}

// -------- 6b. G = mass @ mass.T partials (upper-tri 32x32 tile pairs) --------
__constant__ int c_tpi[10] = {0,0,0,0,1,1,1,2,2,3};
__constant__ int c_tpj[10] = {0,1,2,3,1,2,3,2,3,3};

__global__ __launch_bounds__(64) void k_pairG(const float* __restrict__ mass) {
    __shared__ __align__(16) float sI[32 * 36];
    __shared__ __align__(16) float sJ[32 * 36];
    int tp = blockIdx.x, kb = blockIdx.y;
    int bi = c_tpi[tp], bj = c_tpj[tp];
    int i0 = bi * 32, j0 = bj * 32;
    int t = threadIdx.x;
    int iq = t >> 3, jq = t & 7;           // 8x8 quads of 4: 32x32 tile
    int t0 = kb * 4 + min(kb, 16);         // 128 k-tiles: 16 chunks of 5, 12 of 4
    int nt = 4 + (kb < 16 ? 1 : 0);

    float acc[4][4];
#pragma unroll
    for (int r = 0; r < 4; r++)
#pragma unroll
        for (int c = 0; c < 4; c++) acc[r][c] = 0.f;

    for (int kt = 0; kt < nt; kt++) {
        int lb = (t0 + kt) * 32;
#pragma unroll
        for (int i = 0; i < 16; i++) {
            int idx = t + i * 64;
            int kk = idx & 31, ii = idx >> 5;
            sI[kk * 36 + ii] = mass[(i0 + ii) * NLEAF + lb + kk];
            sJ[kk * 36 + ii] = mass[(j0 + ii) * NLEAF + lb + kk];
        }
        __syncthreads();
#pragma unroll
        for (int k = 0; k < 32; k++) {
            float4 a = *(const float4*)&sI[k * 36 + iq * 4];
            float4 b = *(const float4*)&sJ[k * 36 + jq * 4];
            acc[0][0] += a.x * b.x; acc[0][1] += a.x * b.y; acc[0][2] += a.x * b.z; acc[0][3] += a.x * b.w;
            acc[1][0] += a.y * b.x; acc[1][1] += a.y * b.y; acc[1][2] += a.y * b.z; acc[1][3] += a.y * b.w;
            acc[2][0] += a.z * b.x; acc[2][1] += a.z * b.y; acc[2][2] += a.z * b.z; acc[2][3] += a.z * b.w;
            acc[3][0] += a.w * b.x; acc[3][1] += a.w * b.y; acc[3][2] += a.w * b.z; acc[3][3] += a.w * b.w;
        }
        __syncthreads();
    }
    float* op = g_Gp[kb];
#pragma unroll
    for (int r = 0; r < 4; r++) {
        int i = i0 + iq * 4 + r;
        *(float4*)&op[i * NDOC + j0 + jq * 4] =
            make_float4(acc[r][0], acc[r][1], acc[r][2], acc[r][3]);
    }
    if (bi != bj) {
#pragma unroll
        for (int r = 0; r < 4; r++)
#pragma unroll
            for (int c = 0; c < 4; c++)
                op[(j0 + jq * 4 + c) * NDOC + i0 + iq * 4 + r] = acc[r][c];
    }
}

// -------- 7. inner pairwise x*tanh(x) (16 K-slots of 40 features) --------
__global__ __launch_bounds__(256) void k_pair() {
    __shared__ float sI[32 * 33];
    __shared__ float sJ[32 * 33];
    int tp = blockIdx.x, s = blockIdx.y;
    int bi = c_tpi[tp], bj = c_tpj[tp];
    int i0 = bi * 32, j0 = bj * 32;
    int t = threadIdx.x;
    int tj  = t & 31;
    int tig = t >> 5;

    int k0 = s * 40;
    int k1 = min(k0 + 40, NIN);

    float acc0 = 0.f, acc1 = 0.f, acc2 = 0.f, acc3 = 0.f;

    for (int kt = k0; kt < k1; kt += 32) {
#pragma unroll
        for (int i = 0; i < 4; i++) {
            int idx = t + i * 256;
            int ii = idx & 31, kk = idx >> 5;
            int kg = kt + kk;
            float vI = (kg < k1) ? g_z[kg * NDOC + i0 + ii] : 0.f;
            float vJ = (kg < k1) ? g_z[kg * NDOC + j0 + ii] : 0.f;
            sI[kk * 33 + ii] = vI;
            sJ[kk * 33 + ii] = vJ;
        }
        __syncthreads();
#pragma unroll
        for (int k = 0; k < 32; k++) {
            float b  = sJ[k * 33 + tj];
            float d0 = sI[k * 33 + tig]      - b;
            float d1 = sI[k * 33 + tig + 8]  - b;
            float d2 = sI[k * 33 + tig + 16] - b;
            float d3 = sI[k * 33 + tig + 24] - b;
            acc0 += d0 * tanh_apx(d0);
            acc1 += d1 * tanh_apx(d1);
            acc2 += d2 * tanh_apx(d2);
            acc3 += d3 * tanh_apx(d3);
        }
        __syncthreads();
    }

    float* op = g_outp[s];
    int j = j0 + tj;
    int i;
    i = i0 + tig;      op[i * NDOC + j] = acc0; if (bi != bj) op[j * NDOC + i] = acc0;
    i = i0 + tig + 8;  op[i * NDOC + j] = acc1; if (bi != bj) op[j * NDOC + i] = acc1;
    i = i0 + tig + 16; op[i * NDOC + j] = acc2; if (bi != bj) op[j * NDOC + i] = acc2;
    i = i0 + tig + 24; op[i * NDOC + j] = acc3; if (bi != bj) op[j * NDOC + i] = acc3;
}

// -------- 8. final reduce: out = inner + (n_i + n_j - 2*G) ; exact 0 diagonal --------
__global__ __launch_bounds__(256) void k_reduce(float* __restrict__ out) {
    int idx = blockIdx.x * 256 + threadIdx.x;   // 64*256 = 16384 exact
    int i = idx >> 7, j = idx & 127;
    float gg = 0.f;
#pragma unroll
    for (int kb = 0; kb < GKB; kb++) gg += g_Gp[kb][idx];
    float s = g_n[i] + g_n[j] - 2.0f * gg;      // d_leaf (quadratic smoothabs)
#pragma unroll
    for (int t = 0; t < INNER_SLOTS; t++) s += g_outp[t][idx];
    out[idx] = (i == j) ? 0.f : s;              // true value on diagonal is exactly 0
}

// ---------------- launch ----------------
extern "C" void kernel_launch(void* const* d_in, const int* in_sizes, int n_in,
                              void* d_out, int out_size) {
    const float* mass  = (const float*)d_in[0];   // (128, 4096)
    const float* param = (const float*)d_in[1];   // (625, 4096)
    if (n_in >= 2 && in_sizes[0] == NIN * NLEAF && in_sizes[1] == NDOC * NLEAF) {
        param = (const float*)d_in[0];
        mass  = (const float*)d_in[1];
    }
    float* out = (float*)d_out;

    k_colsum<<<dim3(16, 8), 256>>>(param);
    k_rs<<<16, 256>>>();
    k_gemm<<<dim3(20, GEMM_KB), 256>>>(mass, param);
    k_combine<<<(NIN * NDOC + 255) / 256, 256>>>();
    k_tree<<<1, 1024>>>();
    k_norm<<<16, 256>>>(mass);
    k_pairG<<<dim3(10, GKB), 64>>>(mass);
    k_pair<<<dim3(10, INNER_SLOTS), 256>>>();
    k_reduce<<<64, 256>>>(out);
}

// round 5
// speedup vs baseline: 2.8843x; 1.1396x over previous
#include <cuda_runtime.h>

#define NDOC  128
#define NIN   625
#define NLEAF 4096
#define CSC   16       // colsum row-chunks
#define GEMM_KB 12     // main gemm K-split
#define GKB     12     // G gemm K-split (3 tile-pairs x 12 = 36 blocks)
#define INNER_SLOTS 16 // inner pairwise K-slots

// ---------------- scratch (device globals; no allocation) ----------------
__device__ __align__(16) float g_cs[CSC][NLEAF];
__device__ __align__(16) float g_Wp[GEMM_KB][NIN * NDOC];        // split-K partials of W
__device__ __align__(16) float g_z[NIN * NDOC];                  // z, node-major [p][d]
__device__ __align__(16) float g_outp[INNER_SLOTS][NDOC * NDOC]; // inner pairwise partials
__device__ __align__(16) float g_Gp[GKB][NDOC * NDOC];           // mass@mass.T partials

__device__ __forceinline__ float tanh_apx(float x) {
    float y;
    asm("tanh.approx.f32 %0, %1;" : "=f"(y) : "f"(x));
    return y;
}

// -------- 1. partial column sums of exp(param) --------
__global__ __launch_bounds__(256) void k_colsum(const float* __restrict__ param) {
    int col = blockIdx.x * 256 + threadIdx.x;
    int rc  = blockIdx.y;
    int r0 = rc * 40;
    int r1 = min(r0 + 40, NIN);
    float s = 0.f;
    for (int r = r0; r < r1; r++)
        s += __expf(param[r * NLEAF + col]);
    g_cs[rc][col] = s;
}

// -------- 2. fused big wave: W-gemm (blocks 0..239) + G-gemm (blocks 240..275) --------
// K-chunking (both parts): 128 k-tiles of 32 into 12 chunks: 8 of 11, 4 of 10.
__constant__ int c_gbi[3] = {0, 0, 1};
__constant__ int c_gbj[3] = {0, 1, 1};

__global__ __launch_bounds__(256, 2) void k_big(const float* __restrict__ mass,
                                                const float* __restrict__ param) {
    __shared__ __align__(16) float sbuf[5728];
    int bx = blockIdx.x;
    int t = threadIdx.x;

    if (bx < 240) {
        // ===== W = (mass * rs) @ exp(param).T =====
        float* sA  = sbuf;              // [32][132]
        float* sB  = sbuf + 4224;       // [32][36]
        float* srs = sbuf + 4224 + 1152; // up to 352 cols
        int j0 = (bx % 20) * 32;
        int kb = bx / 20;
        int t0 = kb * 10 + min(kb, 8);
        int nt = 10 + (kb < 8 ? 1 : 0);
        int l0 = t0 * 32;
        int ncol = nt * 32;
        int lane = t & 31;
        int jg = t >> 5;

        // inline rs for this block's K-range
        for (int c = t; c < ncol; c += 256) {
            float s = 0.f;
#pragma unroll
            for (int y = 0; y < CSC; y++) s += g_cs[y][l0 + c];
            srs[c] = 1.0f / s;
        }
        __syncthreads();

        float acc[4][4];
#pragma unroll
        for (int r = 0; r < 4; r++)
#pragma unroll
            for (int c = 0; c < 4; c++) acc[r][c] = 0.f;

        for (int kt = 0; kt < nt; kt++) {
            int lb = (t0 + kt) * 32;
#pragma unroll
            for (int i = 0; i < 16; i++) {
                int idx = t + i * 256;
                int kk = idx & 31, d = idx >> 5;
                sA[kk * 132 + d] = mass[d * NLEAF + lb + kk] * srs[kt * 32 + kk];
            }
#pragma unroll
            for (int i = 0; i < 4; i++) {
                int idx = t + i * 256;
                int kk = idx & 31, jj = idx >> 5;
                int j = j0 + jj;
                sB[kk * 36 + jj] = (j < NIN) ? __expf(param[j * NLEAF + lb + kk]) : 0.f;
            }
            __syncthreads();
#pragma unroll
            for (int k = 0; k < 32; k++) {
                float4 a = *(const float4*)&sA[k * 132 + 4 * lane];
                float4 b = *(const float4*)&sB[k * 36 + jg * 4];
                acc[0][0] += a.x * b.x; acc[0][1] += a.x * b.y; acc[0][2] += a.x * b.z; acc[0][3] += a.x * b.w;
                acc[1][0] += a.y * b.x; acc[1][1] += a.y * b.y; acc[1][2] += a.y * b.z; acc[1][3] += a.y * b.w;
                acc[2][0] += a.z * b.x; acc[2][1] += a.z * b.y; acc[2][2] += a.z * b.z; acc[2][3] += a.z * b.w;
                acc[3][0] += a.w * b.x; acc[3][1] += a.w * b.y; acc[3][2] += a.w * b.z; acc[3][3] += a.w * b.w;
            }
            __syncthreads();
        }
#pragma unroll
        for (int c = 0; c < 4; c++) {
            int j = j0 + jg * 4 + c;
            if (j < NIN)
                *(float4*)&g_Wp[kb][j * NDOC + 4 * lane] =
                    make_float4(acc[0][c], acc[1][c], acc[2][c], acc[3][c]);
        }
    } else {
        // ===== G = mass @ mass.T, 64x64 tiles, 16x16 threads of 4x4 =====
        float* sI = sbuf;               // [32][68]
        float* sJ = sbuf + 2176;        // [32][68]
        int g  = bx - 240;
        int gt = g % 3;
        int kb = g / 3;
        int i0 = c_gbi[gt] * 64, j0 = c_gbj[gt] * 64;
        bool offdiag = (i0 != j0);
        int t0 = kb * 10 + min(kb, 8);
        int nt = 10 + (kb < 8 ? 1 : 0);
        int iq = t >> 4, jq = t & 15;

        float acc[4][4];
#pragma unroll
        for (int r = 0; r < 4; r++)
#pragma unroll
            for (int c = 0; c < 4; c++) acc[r][c] = 0.f;

        for (int kt = 0; kt < nt; kt++) {
            int lb = (t0 + kt) * 32;
#pragma unroll
            for (int i = 0; i < 8; i++) {
                int idx = t + i * 256;
                int kk = idx & 31, ii = idx >> 5;   // ii 0..63
                sI[kk * 68 + ii] = mass[(i0 + ii) * NLEAF + lb + kk];
                sJ[kk * 68 + ii] = mass[(j0 + ii) * NLEAF + lb + kk];
            }
            __syncthreads();
#pragma unroll
            for (int k = 0; k < 32; k++) {
                float4 a = *(const float4*)&sI[k * 68 + iq * 4];
                float4 b = *(const float4*)&sJ[k * 68 + jq * 4];
                acc[0][0] += a.x * b.x; acc[0][1] += a.x * b.y; acc[0][2] += a.x * b.z; acc[0][3] += a.x * b.w;
                acc[1][0] += a.y * b.x; acc[1][1] += a.y * b.y; acc[1][2] += a.y * b.z; acc[1][3] += a.y * b.w;
                acc[2][0] += a.z * b.x; acc[2][1] += a.z * b.y; acc[2][2] += a.z * b.z; acc[2][3] += a.z * b.w;
                acc[3][0] += a.w * b.x; acc[3][1] += a.w * b.y; acc[3][2] += a.w * b.z; acc[3][3] += a.w * b.w;
            }
            __syncthreads();
        }
        float* op = g_Gp[kb];
#pragma unroll
        for (int r = 0; r < 4; r++) {
            int i = i0 + iq * 4 + r;
            *(float4*)&op[i * NDOC + j0 + jq * 4] =
                make_float4(acc[r][0], acc[r][1], acc[r][2], acc[r][3]);
        }
        if (offdiag) {
#pragma unroll
            for (int r = 0; r < 4; r++)
#pragma unroll
                for (int c = 0; c < 4; c++)
                    op[(j0 + jq * 4 + c) * NDOC + i0 + iq * 4 + r] = acc[r][c];
        }
    }
}

// -------- 3. combine split-K partials --------
__global__ __launch_bounds__(256) void k_combine() {
    int idx = blockIdx.x * 256 + threadIdx.x;
    if (idx < NIN * NDOC) {
        float s = 0.f;
#pragma unroll
        for (int kb = 0; kb < GEMM_KB; kb++) s += g_Wp[kb][idx];
        g_z[idx] = s;
    }
}

// -------- 4. bottom-up subtree sums, level-parallel, float4 --------
__global__ __launch_bounds__(1024) void k_tree() {
    float4* z4 = (float4*)g_z;
    int t = threadIdx.x;
    for (int i = t; i < 94 * 32; i += 1024) {
        int p = 31 + (i >> 5), q = i & 31;
        float4 s = z4[p * 32 + q];
        int c0 = 5 * p + 1, c1 = min(c0 + 5, NIN);
        for (int c = c0; c < c1; c++) {
            float4 v = z4[c * 32 + q];
            s.x += v.x; s.y += v.y; s.z += v.z; s.w += v.w;
        }
        z4[p * 32 + q] = s;
    }
    __syncthreads();
    for (int i = t; i < 25 * 32; i += 1024) {
        int p = 6 + (i >> 5), q = i & 31;
        float4 s = z4[p * 32 + q];
        int c0 = 5 * p + 1;
        for (int c = c0; c < c0 + 5; c++) {
            float4 v = z4[c * 32 + q];
            s.x += v.x; s.y += v.y; s.z += v.z; s.w += v.w;
        }
        z4[p * 32 + q] = s;
    }
    __syncthreads();
    if (t < 5 * 32) {
        int p = 1 + (t >> 5), q = t & 31;
        float4 s = z4[p * 32 + q];
        int c0 = 5 * p + 1;
        for (int c = c0; c < c0 + 5; c++) {
            float4 v = z4[c * 32 + q];
            s.x += v.x; s.y += v.y; s.z += v.z; s.w += v.w;
        }
        z4[p * 32 + q] = s;
    }
    __syncthreads();
    if (t < 32) {
        float4 s = z4[t];
        for (int c = 1; c <= 5; c++) {
            float4 v = z4[c * 32 + t];
            s.x += v.x; s.y += v.y; s.z += v.z; s.w += v.w;
        }
        z4[t] = s;
    }
}

// -------- 5. inner pairwise x*tanh(x) (16 K-slots of 40 features) --------
__constant__ int c_tpi[10] = {0,0,0,0,1,1,1,2,2,3};
__constant__ int c_tpj[10] = {0,1,2,3,1,2,3,2,3,3};

__global__ __launch_bounds__(256) void k_pair() {
    __shared__ float sI[32 * 33];
    __shared__ float sJ[32 * 33];
    int tp = blockIdx.x, s = blockIdx.y;
    int bi = c_tpi[tp], bj = c_tpj[tp];
    int i0 = bi * 32, j0 = bj * 32;
    int t = threadIdx.x;
    int tj  = t & 31;
    int tig = t >> 5;

    int k0 = s * 40;
    int k1 = min(k0 + 40, NIN);

    float acc0 = 0.f, acc1 = 0.f, acc2 = 0.f, acc3 = 0.f;

    for (int kt = k0; kt < k1; kt += 32) {
#pragma unroll
        for (int i = 0; i < 4; i++) {
            int idx = t + i * 256;
            int ii = idx & 31, kk = idx >> 5;
            int kg = kt + kk;
            float vI = (kg < k1) ? g_z[kg * NDOC + i0 + ii] : 0.f;
            float vJ = (kg < k1) ? g_z[kg * NDOC + j0 + ii] : 0.f;
            sI[kk * 33 + ii] = vI;
            sJ[kk * 33 + ii] = vJ;
        }
        __syncthreads();
#pragma unroll
        for (int k = 0; k < 32; k++) {
            float b  = sJ[k * 33 + tj];
            float d0 = sI[k * 33 + tig]      - b;
            float d1 = sI[k * 33 + tig + 8]  - b;
            float d2 = sI[k * 33 + tig + 16] - b;
            float d3 = sI[k * 33 + tig + 24] - b;
            acc0 += d0 * tanh_apx(d0);
            acc1 += d1 * tanh_apx(d1);
            acc2 += d2 * tanh_apx(d2);
            acc3 += d3 * tanh_apx(d3);
        }
        __syncthreads();
    }

    float* op = g_outp[s];
    int j = j0 + tj;
    int i;
    i = i0 + tig;      op[i * NDOC + j] = acc0; if (bi != bj) op[j * NDOC + i] = acc0;
    i = i0 + tig + 8;  op[i * NDOC + j] = acc1; if (bi != bj) op[j * NDOC + i] = acc1;
    i = i0 + tig + 16; op[i * NDOC + j] = acc2; if (bi != bj) op[j * NDOC + i] = acc2;
    i = i0 + tig + 24; op[i * NDOC + j] = acc3; if (bi != bj) op[j * NDOC + i] = acc3;
}

// -------- 6. final reduce: out = inner + (G_ii + G_jj - 2*G_ij); exact 0 diagonal --------
__global__ __launch_bounds__(256) void k_reduce(float* __restrict__ out) {
    int idx = blockIdx.x * 256 + threadIdx.x;   // 64*256 = 16384 exact
    int i = idx >> 7, j = idx & 127;
    float gg = 0.f, ni = 0.f, nj = 0.f;
#pragma unroll
    for (int kb = 0; kb < GKB; kb++) {
        gg += g_Gp[kb][idx];
        ni += g_Gp[kb][i * (NDOC + 1)];
        nj += g_Gp[kb][j * (NDOC + 1)];
    }
    float s = ni + nj - 2.0f * gg;              // d_leaf (quadratic smoothabs)
#pragma unroll
    for (int t = 0; t < INNER_SLOTS; t++) s += g_outp[t][idx];
    out[idx] = (i == j) ? 0.f : s;
}

// ---------------- launch ----------------
extern "C" void kernel_launch(void* const* d_in, const int* in_sizes, int n_in,
                              void* d_out, int out_size) {
    const float* mass  = (const float*)d_in[0];   // (128, 4096)
    const float* param = (const float*)d_in[1];   // (625, 4096)
    if (n_in >= 2 && in_sizes[0] == NIN * NLEAF && in_sizes[1] == NDOC * NLEAF) {
        param = (const float*)d_in[0];
        mass  = (const float*)d_in[1];
    }
    float* out = (float*)d_out;

    k_colsum<<<dim3(16, CSC), 256>>>(param);
    k_big<<<240 + 3 * GKB, 256>>>(mass, param);
    k_combine<<<(NIN * NDOC + 255) / 256, 256>>>();
    k_tree<<<1, 1024>>>();
    k_pair<<<dim3(10, INNER_SLOTS), 256>>>();
    k_reduce<<<64, 256>>>(out);
}

// round 6
// speedup vs baseline: 2.8956x; 1.0039x over previous
#include <cuda_runtime.h>

#define NDOC  128
#define NIN   625
#define NLEAF 4096
#define CSC   16       // colsum row-chunks
#define GEMM_KB 12     // main gemm K-split
#define GKB     12     // G gemm K-split (3 tile-pairs x 12 = 36 blocks)
#define INNER_SLOTS 16 // inner pairwise K-slots

// ---------------- scratch (device globals; no allocation) ----------------
__device__ __align__(16) float g_cs[CSC][NLEAF];
__device__ __align__(16) float g_Wp[GEMM_KB][NIN * NDOC];        // split-K partials of W
__device__ __align__(16) float g_z[NIN * NDOC];                  // z, node-major [p][d]
__device__ __align__(16) float g_outp[INNER_SLOTS][NDOC * NDOC]; // inner pairwise partials
__device__ __align__(16) float g_Gp[GKB][NDOC * NDOC];           // mass@mass.T partials

__device__ __forceinline__ float tanh_apx(float x) {
    float y;
    asm("tanh.approx.f32 %0, %1;" : "=f"(y) : "f"(x));
    return y;
}

// -------- 1. partial column sums of exp(param) --------
__global__ __launch_bounds__(256) void k_colsum(const float* __restrict__ param) {
    int col = blockIdx.x * 256 + threadIdx.x;
    int rc  = blockIdx.y;
    int r0 = rc * 40;
    int r1 = min(r0 + 40, NIN);
    float s = 0.f;
    for (int r = r0; r < r1; r++)
        s += __expf(param[r * NLEAF + col]);
    g_cs[rc][col] = s;
}

// -------- 2. fused big wave: W-gemm (blocks 0..239) + G-gemm (blocks 240..275) --------
__constant__ int c_gbi[3] = {0, 0, 1};
__constant__ int c_gbj[3] = {0, 1, 1};

__global__ __launch_bounds__(256, 2) void k_big(const float* __restrict__ mass,
                                                const float* __restrict__ param) {
    __shared__ __align__(16) float sbuf[5728];
    int bx = blockIdx.x;
    int t = threadIdx.x;

    if (bx < 240) {
        // ===== W = (mass * rs) @ exp(param).T =====
        float* sA  = sbuf;               // [32][132]
        float* sB  = sbuf + 4224;        // [32][36]
        float* srs = sbuf + 4224 + 1152; // up to 352 cols
        int j0 = (bx % 20) * 32;
        int kb = bx / 20;
        int t0 = kb * 10 + min(kb, 8);
        int nt = 10 + (kb < 8 ? 1 : 0);
        int l0 = t0 * 32;
        int ncol = nt * 32;
        int lane = t & 31;
        int jg = t >> 5;

        for (int c = t; c < ncol; c += 256) {
            float s = 0.f;
#pragma unroll
            for (int y = 0; y < CSC; y++) s += g_cs[y][l0 + c];
            srs[c] = 1.0f / s;
        }
        __syncthreads();

        float acc[4][4];
#pragma unroll
        for (int r = 0; r < 4; r++)
#pragma unroll
            for (int c = 0; c < 4; c++) acc[r][c] = 0.f;

        for (int kt = 0; kt < nt; kt++) {
            int lb = (t0 + kt) * 32;
#pragma unroll
            for (int i = 0; i < 16; i++) {
                int idx = t + i * 256;
                int kk = idx & 31, d = idx >> 5;
                sA[kk * 132 + d] = mass[d * NLEAF + lb + kk] * srs[kt * 32 + kk];
            }
#pragma unroll
            for (int i = 0; i < 4; i++) {
                int idx = t + i * 256;
                int kk = idx & 31, jj = idx >> 5;
                int j = j0 + jj;
                sB[kk * 36 + jj] = (j < NIN) ? __expf(param[j * NLEAF + lb + kk]) : 0.f;
            }
            __syncthreads();
#pragma unroll
            for (int k = 0; k < 32; k++) {
                float4 a = *(const float4*)&sA[k * 132 + 4 * lane];
                float4 b = *(const float4*)&sB[k * 36 + jg * 4];
                acc[0][0] += a.x * b.x; acc[0][1] += a.x * b.y; acc[0][2] += a.x * b.z; acc[0][3] += a.x * b.w;
                acc[1][0] += a.y * b.x; acc[1][1] += a.y * b.y; acc[1][2] += a.y * b.z; acc[1][3] += a.y * b.w;
                acc[2][0] += a.z * b.x; acc[2][1] += a.z * b.y; acc[2][2] += a.z * b.z; acc[2][3] += a.z * b.w;
                acc[3][0] += a.w * b.x; acc[3][1] += a.w * b.y; acc[3][2] += a.w * b.z; acc[3][3] += a.w * b.w;
            }
            __syncthreads();
        }
#pragma unroll
        for (int c = 0; c < 4; c++) {
            int j = j0 + jg * 4 + c;
            if (j < NIN)
                *(float4*)&g_Wp[kb][j * NDOC + 4 * lane] =
                    make_float4(acc[0][c], acc[1][c], acc[2][c], acc[3][c]);
        }
    } else {
        // ===== G = mass @ mass.T, 64x64 tiles, 16x16 threads of 4x4 =====
        float* sI = sbuf;               // [32][68]
        float* sJ = sbuf + 2176;        // [32][68]
        int g  = bx - 240;
        int gt = g % 3;
        int kb = g / 3;
        int i0 = c_gbi[gt] * 64, j0 = c_gbj[gt] * 64;
        bool offdiag = (i0 != j0);
        int t0 = kb * 10 + min(kb, 8);
        int nt = 10 + (kb < 8 ? 1 : 0);
        int iq = t >> 4, jq = t & 15;

        float acc[4][4];
#pragma unroll
        for (int r = 0; r < 4; r++)
#pragma unroll
            for (int c = 0; c < 4; c++) acc[r][c] = 0.f;

        for (int kt = 0; kt < nt; kt++) {
            int lb = (t0 + kt) * 32;
#pragma unroll
            for (int i = 0; i < 8; i++) {
                int idx = t + i * 256;
                int kk = idx & 31, ii = idx >> 5;
                sI[kk * 68 + ii] = mass[(i0 + ii) * NLEAF + lb + kk];
                sJ[kk * 68 + ii] = mass[(j0 + ii) * NLEAF + lb + kk];
            }
            __syncthreads();
#pragma unroll
            for (int k = 0; k < 32; k++) {
                float4 a = *(const float4*)&sI[k * 68 + iq * 4];
                float4 b = *(const float4*)&sJ[k * 68 + jq * 4];
                acc[0][0] += a.x * b.x; acc[0][1] += a.x * b.y; acc[0][2] += a.x * b.z; acc[0][3] += a.x * b.w;
                acc[1][0] += a.y * b.x; acc[1][1] += a.y * b.y; acc[1][2] += a.y * b.z; acc[1][3] += a.y * b.w;
                acc[2][0] += a.z * b.x; acc[2][1] += a.z * b.y; acc[2][2] += a.z * b.z; acc[2][3] += a.z * b.w;
                acc[3][0] += a.w * b.x; acc[3][1] += a.w * b.y; acc[3][2] += a.w * b.z; acc[3][3] += a.w * b.w;
            }
            __syncthreads();
        }
        float* op = g_Gp[kb];
#pragma unroll
        for (int r = 0; r < 4; r++) {
            int i = i0 + iq * 4 + r;
            *(float4*)&op[i * NDOC + j0 + jq * 4] =
                make_float4(acc[r][0], acc[r][1], acc[r][2], acc[r][3]);
        }
        if (offdiag) {
#pragma unroll
            for (int r = 0; r < 4; r++)
#pragma unroll
                for (int c = 0; c < 4; c++)
                    op[(j0 + jq * 4 + c) * NDOC + i0 + iq * 4 + r] = acc[r][c];
        }
    }
}

// -------- 3. combine split-K partials + tree phase 1 fused --------
// For parents 31..124 (children 156..624 are childless), the subtree sum is
// computed directly from the partials: z[p] = sum_kb Wp[p] + sum_children sum_kb Wp[c].
__global__ __launch_bounds__(256) void k_combine() {
    int idx = blockIdx.x * 256 + threadIdx.x;
    if (idx < NIN * NDOC) {
        int n = idx >> 7, d = idx & 127;
        float s = 0.f;
#pragma unroll
        for (int kb = 0; kb < GEMM_KB; kb++) s += g_Wp[kb][idx];
        if (n >= 31 && n <= 124) {
            int c0 = 5 * n + 1;
            int c1 = min(c0 + 5, NIN);
            for (int c = c0; c < c1; c++) {
                int cidx = c * NDOC + d;
#pragma unroll
                for (int kb = 0; kb < GEMM_KB; kb++) s += g_Wp[kb][cidx];
            }
        }
        g_z[idx] = s;
    }
}

// -------- 4. tree phases 2-4 only (31 parents), tiny latency kernel --------
__global__ __launch_bounds__(1024) void k_tree234() {
    float4* z4 = (float4*)g_z;   // 32 float4 per node row
    int t = threadIdx.x;
    // phase 2: parents 6..30 (children 31..155 already subtree-complete)
    if (t < 25 * 32) {
        int p = 6 + (t >> 5), q = t & 31;
        float4 s = z4[p * 32 + q];
        int c0 = 5 * p + 1;
        for (int c = c0; c < c0 + 5; c++) {
            float4 v = z4[c * 32 + q];
            s.x += v.x; s.y += v.y; s.z += v.z; s.w += v.w;
        }
        z4[p * 32 + q] = s;
    }
    __syncthreads();
    // phase 3: parents 1..5
    if (t < 5 * 32) {
        int p = 1 + (t >> 5), q = t & 31;
        float4 s = z4[p * 32 + q];
        int c0 = 5 * p + 1;
        for (int c = c0; c < c0 + 5; c++) {
            float4 v = z4[c * 32 + q];
            s.x += v.x; s.y += v.y; s.z += v.z; s.w += v.w;
        }
        z4[p * 32 + q] = s;
    }
    __syncthreads();
    // phase 4: root
    if (t < 32) {
        float4 s = z4[t];
        for (int c = 1; c <= 5; c++) {
            float4 v = z4[c * 32 + t];
            s.x += v.x; s.y += v.y; s.z += v.z; s.w += v.w;
        }
        z4[t] = s;
    }
}

// -------- 5. inner pairwise x*tanh(x) (16 K-slots of 40 features) --------
__constant__ int c_tpi[10] = {0,0,0,0,1,1,1,2,2,3};
__constant__ int c_tpj[10] = {0,1,2,3,1,2,3,2,3,3};

__global__ __launch_bounds__(256) void k_pair() {
    __shared__ float sI[32 * 33];
    __shared__ float sJ[32 * 33];
    int tp = blockIdx.x, s = blockIdx.y;
    int bi = c_tpi[tp], bj = c_tpj[tp];
    int i0 = bi * 32, j0 = bj * 32;
    int t = threadIdx.x;
    int tj  = t & 31;
    int tig = t >> 5;

    int k0 = s * 40;
    int k1 = min(k0 + 40, NIN);

    float acc0 = 0.f, acc1 = 0.f, acc2 = 0.f, acc3 = 0.f;

    for (int kt = k0; kt < k1; kt += 32) {
#pragma unroll
        for (int i = 0; i < 4; i++) {
            int idx = t + i * 256;
            int ii = idx & 31, kk = idx >> 5;
            int kg = kt + kk;
            float vI = (kg < k1) ? g_z[kg * NDOC + i0 + ii] : 0.f;
            float vJ = (kg < k1) ? g_z[kg * NDOC + j0 + ii] : 0.f;
            sI[kk * 33 + ii] = vI;
            sJ[kk * 33 + ii] = vJ;
        }
        __syncthreads();
#pragma unroll
        for (int k = 0; k < 32; k++) {
            float b  = sJ[k * 33 + tj];
            float d0 = sI[k * 33 + tig]      - b;
            float d1 = sI[k * 33 + tig + 8]  - b;
            float d2 = sI[k * 33 + tig + 16] - b;
            float d3 = sI[k * 33 + tig + 24] - b;
            acc0 += d0 * tanh_apx(d0);
            acc1 += d1 * tanh_apx(d1);
            acc2 += d2 * tanh_apx(d2);
            acc3 += d3 * tanh_apx(d3);
        }
        __syncthreads();
    }

    float* op = g_outp[s];
    int j = j0 + tj;
    int i;
    i = i0 + tig;      op[i * NDOC + j] = acc0; if (bi != bj) op[j * NDOC + i] = acc0;
    i = i0 + tig + 8;  op[i * NDOC + j] = acc1; if (bi != bj) op[j * NDOC + i] = acc1;
    i = i0 + tig + 16; op[i * NDOC + j] = acc2; if (bi != bj) op[j * NDOC + i] = acc2;
    i = i0 + tig + 24; op[i * NDOC + j] = acc3; if (bi != bj) op[j * NDOC + i] = acc3;
}

// -------- 6. final reduce: out = inner + (G_ii + G_jj - 2*G_ij); exact 0 diagonal --------
__global__ __launch_bounds__(256) void k_reduce(float* __restrict__ out) {
    int idx = blockIdx.x * 256 + threadIdx.x;   // 64*256 = 16384 exact
    int i = idx >> 7, j = idx & 127;
    float gg = 0.f, ni = 0.f, nj = 0.f;
#pragma unroll
    for (int kb = 0; kb < GKB; kb++) {
        gg += g_Gp[kb][idx];
        ni += g_Gp[kb][i * (NDOC + 1)];
        nj += g_Gp[kb][j * (NDOC + 1)];
    }
    float s = ni + nj - 2.0f * gg;              // d_leaf (quadratic smoothabs)
#pragma unroll
    for (int t = 0; t < INNER_SLOTS; t++) s += g_outp[t][idx];
    out[idx] = (i == j) ? 0.f : s;
}

// ---------------- launch ----------------
extern "C" void kernel_launch(void* const* d_in, const int* in_sizes, int n_in,
                              void* d_out, int out_size) {
    const float* mass  = (const float*)d_in[0];   // (128, 4096)
    const float* param = (const float*)d_in[1];   // (625, 4096)
    if (n_in >= 2 && in_sizes[0] == NIN * NLEAF && in_sizes[1] == NDOC * NLEAF) {
        param = (const float*)d_in[0];
        mass  = (const float*)d_in[1];
    }
    float* out = (float*)d_out;

    k_colsum<<<dim3(16, CSC), 256>>>(param);
    k_big<<<240 + 3 * GKB, 256>>>(mass, param);
    k_combine<<<(NIN * NDOC + 255) / 256, 256>>>();
    k_tree234<<<1, 1024>>>();
    k_pair<<<dim3(10, INNER_SLOTS), 256>>>();
    k_reduce<<<64, 256>>>(out);
}

// round 7
// speedup vs baseline: 2.9925x; 1.0335x over previous
#include <cuda_runtime.h>

#define NDOC  128
#define NIN   625
#define NLEAF 4096
#define CSC   16       // colsum row-chunks
#define GEMM_KB 12     // main gemm K-split
#define GKB     12     // G gemm K-split (3 tile-pairs x 12 = 36 blocks)
#define INNER_SLOTS 16 // inner pairwise K-slots

// ---------------- scratch (device globals; no allocation) ----------------
__device__ __align__(16) float g_cs[CSC][NLEAF];
__device__ __align__(16) float g_Wp[GEMM_KB][NIN * NDOC];        // split-K partials of W
__device__ __align__(16) float g_z[NIN * NDOC];                  // z, node-major [p][d]
__device__ __align__(16) float g_outp[INNER_SLOTS][NDOC * NDOC]; // inner pairwise partials
__device__ __align__(16) float g_Gp[GKB][NDOC * NDOC];           // mass@mass.T partials

__device__ __forceinline__ float tanh_apx(float x) {
    float y;
    asm("tanh.approx.f32 %0, %1;" : "=f"(y) : "f"(x));
    return y;
}

// -------- 1. partial column sums of exp(param) --------
__global__ __launch_bounds__(256) void k_colsum(const float* __restrict__ param) {
    int col = blockIdx.x * 256 + threadIdx.x;
    int rc  = blockIdx.y;
    int r0 = rc * 40;
    int r1 = min(r0 + 40, NIN);
    float s = 0.f;
    for (int r = r0; r < r1; r++)
        s += __expf(param[r * NLEAF + col]);
    g_cs[rc][col] = s;
}

// -------- 2. fused big wave: W-gemm (blocks 0..239) + G-gemm (blocks 240..275) --------
__constant__ int c_gbi[3] = {0, 0, 1};
__constant__ int c_gbj[3] = {0, 1, 1};

__global__ __launch_bounds__(256, 2) void k_big(const float* __restrict__ mass,
                                                const float* __restrict__ param) {
    __shared__ __align__(16) float sbuf[5728];
    int bx = blockIdx.x;
    int t = threadIdx.x;

    if (bx < 240) {
        // ===== W = (mass * rs) @ exp(param).T =====
        float* sA  = sbuf;               // [32][132]
        float* sB  = sbuf + 4224;        // [32][36]
        float* srs = sbuf + 4224 + 1152; // up to 352 cols
        int j0 = (bx % 20) * 32;
        int kb = bx / 20;
        int t0 = kb * 10 + min(kb, 8);
        int nt = 10 + (kb < 8 ? 1 : 0);
        int l0 = t0 * 32;
        int ncol = nt * 32;
        int lane = t & 31;
        int jg = t >> 5;

        for (int c = t; c < ncol; c += 256) {
            float s = 0.f;
#pragma unroll
            for (int y = 0; y < CSC; y++) s += g_cs[y][l0 + c];
            srs[c] = 1.0f / s;
        }
        __syncthreads();

        float acc[4][4];
#pragma unroll
        for (int r = 0; r < 4; r++)
#pragma unroll
            for (int c = 0; c < 4; c++) acc[r][c] = 0.f;

        for (int kt = 0; kt < nt; kt++) {
            int lb = (t0 + kt) * 32;
#pragma unroll
            for (int i = 0; i < 16; i++) {
                int idx = t + i * 256;
                int kk = idx & 31, d = idx >> 5;
                sA[kk * 132 + d] = mass[d * NLEAF + lb + kk] * srs[kt * 32 + kk];
            }
#pragma unroll
            for (int i = 0; i < 4; i++) {
                int idx = t + i * 256;
                int kk = idx & 31, jj = idx >> 5;
                int j = j0 + jj;
                sB[kk * 36 + jj] = (j < NIN) ? __expf(param[j * NLEAF + lb + kk]) : 0.f;
            }
            __syncthreads();
#pragma unroll
            for (int k = 0; k < 32; k++) {
                float4 a = *(const float4*)&sA[k * 132 + 4 * lane];
                float4 b = *(const float4*)&sB[k * 36 + jg * 4];
                acc[0][0] += a.x * b.x; acc[0][1] += a.x * b.y; acc[0][2] += a.x * b.z; acc[0][3] += a.x * b.w;
                acc[1][0] += a.y * b.x; acc[1][1] += a.y * b.y; acc[1][2] += a.y * b.z; acc[1][3] += a.y * b.w;
                acc[2][0] += a.z * b.x; acc[2][1] += a.z * b.y; acc[2][2] += a.z * b.z; acc[2][3] += a.z * b.w;
                acc[3][0] += a.w * b.x; acc[3][1] += a.w * b.y; acc[3][2] += a.w * b.z; acc[3][3] += a.w * b.w;
            }
            __syncthreads();
        }
#pragma unroll
        for (int c = 0; c < 4; c++) {
            int j = j0 + jg * 4 + c;
            if (j < NIN)
                *(float4*)&g_Wp[kb][j * NDOC + 4 * lane] =
                    make_float4(acc[0][c], acc[1][c], acc[2][c], acc[3][c]);
        }
    } else {
        // ===== G = mass @ mass.T, 64x64 tiles, 16x16 threads of 4x4 =====
        float* sI = sbuf;               // [32][68]
        float* sJ = sbuf + 2176;        // [32][68]
        int g  = bx - 240;
        int gt = g % 3;
        int kb = g / 3;
        int i0 = c_gbi[gt] * 64, j0 = c_gbj[gt] * 64;
        bool offdiag = (i0 != j0);
        int t0 = kb * 10 + min(kb, 8);
        int nt = 10 + (kb < 8 ? 1 : 0);
        int iq = t >> 4, jq = t & 15;

        float acc[4][4];
#pragma unroll
        for (int r = 0; r < 4; r++)
#pragma unroll
            for (int c = 0; c < 4; c++) acc[r][c] = 0.f;

        for (int kt = 0; kt < nt; kt++) {
            int lb = (t0 + kt) * 32;
#pragma unroll
            for (int i = 0; i < 8; i++) {
                int idx = t + i * 256;
                int kk = idx & 31, ii = idx >> 5;
                sI[kk * 68 + ii] = mass[(i0 + ii) * NLEAF + lb + kk];
                sJ[kk * 68 + ii] = mass[(j0 + ii) * NLEAF + lb + kk];
            }
            __syncthreads();
#pragma unroll
            for (int k = 0; k < 32; k++) {
                float4 a = *(const float4*)&sI[k * 68 + iq * 4];
                float4 b = *(const float4*)&sJ[k * 68 + jq * 4];
                acc[0][0] += a.x * b.x; acc[0][1] += a.x * b.y; acc[0][2] += a.x * b.z; acc[0][3] += a.x * b.w;
                acc[1][0] += a.y * b.x; acc[1][1] += a.y * b.y; acc[1][2] += a.y * b.z; acc[1][3] += a.y * b.w;
                acc[2][0] += a.z * b.x; acc[2][1] += a.z * b.y; acc[2][2] += a.z * b.z; acc[2][3] += a.z * b.w;
                acc[3][0] += a.w * b.x; acc[3][1] += a.w * b.y; acc[3][2] += a.w * b.z; acc[3][3] += a.w * b.w;
            }
            __syncthreads();
        }
        float* op = g_Gp[kb];
#pragma unroll
        for (int r = 0; r < 4; r++) {
            int i = i0 + iq * 4 + r;
            *(float4*)&op[i * NDOC + j0 + jq * 4] =
                make_float4(acc[r][0], acc[r][1], acc[r][2], acc[r][3]);
        }
        if (offdiag) {
#pragma unroll
            for (int r = 0; r < 4; r++)
#pragma unroll
                for (int c = 0; c < 4; c++)
                    op[(j0 + jq * 4 + c) * NDOC + i0 + iq * 4 + r] = acc[r][c];
        }
    }
}

// -------- 3. combine split-K partials + tree phase 1 fused --------
// After this kernel: g_z holds SUBTREE sums for nodes 31..124, plain W for
// childless nodes 125..624 (= their subtree sums), plain W for nodes 0..30.
// Nodes 0..30's subtree sums are computed locally in k_pair (slot 0 only).
__global__ __launch_bounds__(256) void k_combine() {
    int idx = blockIdx.x * 256 + threadIdx.x;
    if (idx < NIN * NDOC) {
        int n = idx >> 7, d = idx & 127;
        float s = 0.f;
#pragma unroll
        for (int kb = 0; kb < GEMM_KB; kb++) s += g_Wp[kb][idx];
        if (n >= 31 && n <= 124) {
            int c0 = 5 * n + 1;
            int c1 = min(c0 + 5, NIN);
            for (int c = c0; c < c1; c++) {
                int cidx = c * NDOC + d;
#pragma unroll
                for (int kb = 0; kb < GEMM_KB; kb++) s += g_Wp[kb][cidx];
            }
        }
        g_z[idx] = s;
    }
}

// -------- 4. inner pairwise x*tanh(x) (16 K-slots of 40 features) --------
// Slot 0 blocks compute subtree sums for nodes 0..30 locally in smem (uzI/uzJ)
// before the main loop; their kt=0 tile reads from that buffer.
__constant__ int c_tpi[10] = {0,0,0,0,1,1,1,2,2,3};
__constant__ int c_tpj[10] = {0,1,2,3,1,2,3,2,3,3};

__global__ __launch_bounds__(256) void k_pair() {
    __shared__ float sI[32 * 33];
    __shared__ float sJ[32 * 33];
    __shared__ float uzI[32 * 33];   // rows 0..30: local subtree sums; row 31: copy of z[31]
    __shared__ float uzJ[32 * 33];
    int tp = blockIdx.x, s = blockIdx.y;
    int bi = c_tpi[tp], bj = c_tpj[tp];
    int i0 = bi * 32, j0 = bj * 32;
    int t = threadIdx.x;
    int tj  = t & 31;
    int tig = t >> 5;

    if (s == 0) {
        // phase A: parents 6..30 (children 31..155 complete in g_z) + row 31 copy
        for (int it = t; it < 25 * 64 + 64; it += 256) {
            if (it < 25 * 64) {
                int p = 6 + (it >> 6), dd = it & 63;
                int doc = (dd < 32) ? i0 + dd : j0 + (dd - 32);
                float sv = g_z[p * NDOC + doc];
                int c0 = 5 * p + 1;
#pragma unroll
                for (int c = 0; c < 5; c++) sv += g_z[(c0 + c) * NDOC + doc];
                float* dst = (dd < 32) ? uzI : uzJ;
                dst[p * 33 + (dd & 31)] = sv;
            } else {
                int dd = it - 25 * 64;
                int doc = (dd < 32) ? i0 + dd : j0 + (dd - 32);
                float* dst = (dd < 32) ? uzI : uzJ;
                dst[31 * 33 + (dd & 31)] = g_z[31 * NDOC + doc];
            }
        }
        __syncthreads();
        // phase B: parents 1..5 (children 6..30 in uz)
        if (t < 5 * 64) {
            int p = 1 + (t >> 6), dd = t & 63;
            int doc = (dd < 32) ? i0 + dd : j0 + (dd - 32);
            float* buf = (dd < 32) ? uzI : uzJ;
            float sv = g_z[p * NDOC + doc];
            int c0 = 5 * p + 1;
#pragma unroll
            for (int c = 0; c < 5; c++) sv += buf[(c0 + c) * 33 + (dd & 31)];
            buf[p * 33 + (dd & 31)] = sv;
        }
        __syncthreads();
        // phase C: root (children 1..5 in uz)
        if (t < 64) {
            int dd = t;
            int doc = (dd < 32) ? i0 + dd : j0 + (dd - 32);
            float* buf = (dd < 32) ? uzI : uzJ;
            float sv = g_z[doc];
#pragma unroll
            for (int c = 1; c <= 5; c++) sv += buf[c * 33 + (dd & 31)];
            buf[(dd & 31)] = sv;
        }
        __syncthreads();
    }

    int k0 = s * 40;
    int k1 = min(k0 + 40, NIN);

    float acc0 = 0.f, acc1 = 0.f, acc2 = 0.f, acc3 = 0.f;

    for (int kt = k0; kt < k1; kt += 32) {
        const float* pI;
        const float* pJ;
        if (s == 0 && kt == 0) {
            pI = uzI; pJ = uzJ;        // nodes 0..31 already staged
        } else {
#pragma unroll
            for (int i = 0; i < 4; i++) {
                int idx = t + i * 256;
                int ii = idx & 31, kk = idx >> 5;
                int kg = kt + kk;
                float vI = (kg < k1) ? g_z[kg * NDOC + i0 + ii] : 0.f;
                float vJ = (kg < k1) ? g_z[kg * NDOC + j0 + ii] : 0.f;
                sI[kk * 33 + ii] = vI;
                sJ[kk * 33 + ii] = vJ;
            }
            __syncthreads();
            pI = sI; pJ = sJ;
        }
#pragma unroll
        for (int k = 0; k < 32; k++) {
            float b  = pJ[k * 33 + tj];
            float d0 = pI[k * 33 + tig]      - b;
            float d1 = pI[k * 33 + tig + 8]  - b;
            float d2 = pI[k * 33 + tig + 16] - b;
            float d3 = pI[k * 33 + tig + 24] - b;
            acc0 += d0 * tanh_apx(d0);
            acc1 += d1 * tanh_apx(d1);
            acc2 += d2 * tanh_apx(d2);
            acc3 += d3 * tanh_apx(d3);
        }
        __syncthreads();
    }

    float* op = g_outp[s];
    int j = j0 + tj;
    int i;
    i = i0 + tig;      op[i * NDOC + j] = acc0; if (bi != bj) op[j * NDOC + i] = acc0;
    i = i0 + tig + 8;  op[i * NDOC + j] = acc1; if (bi != bj) op[j * NDOC + i] = acc1;
    i = i0 + tig + 16; op[i * NDOC + j] = acc2; if (bi != bj) op[j * NDOC + i] = acc2;
    i = i0 + tig + 24; op[i * NDOC + j] = acc3; if (bi != bj) op[j * NDOC + i] = acc3;
}

// -------- 5. final reduce: out = inner + (G_ii + G_jj - 2*G_ij); exact 0 diagonal --------
__global__ __launch_bounds__(256) void k_reduce(float* __restrict__ out) {
    int idx = blockIdx.x * 256 + threadIdx.x;   // 64*256 = 16384 exact
    int i = idx >> 7, j = idx & 127;
    float gg = 0.f, ni = 0.f, nj = 0.f;
#pragma unroll
    for (int kb = 0; kb < GKB; kb++) {
        gg += g_Gp[kb][idx];
        ni += g_Gp[kb][i * (NDOC + 1)];
        nj += g_Gp[kb][j * (NDOC + 1)];
    }
    float s = ni + nj - 2.0f * gg;              // d_leaf (quadratic smoothabs)
#pragma unroll
    for (int t = 0; t < INNER_SLOTS; t++) s += g_outp[t][idx];
    out[idx] = (i == j) ? 0.f : s;
}

// ---------------- launch ----------------
extern "C" void kernel_launch(void* const* d_in, const int* in_sizes, int n_in,
                              void* d_out, int out_size) {
    const float* mass  = (const float*)d_in[0];   // (128, 4096)
    const float* param = (const float*)d_in[1];   // (625, 4096)
    if (n_in >= 2 && in_sizes[0] == NIN * NLEAF && in_sizes[1] == NDOC * NLEAF) {
        param = (const float*)d_in[0];
        mass  = (const float*)d_in[1];
    }
    float* out = (float*)d_out;

    k_colsum<<<dim3(16, CSC), 256>>>(param);
    k_big<<<240 + 3 * GKB, 256>>>(mass, param);
    k_combine<<<(NIN * NDOC + 255) / 256, 256>>>();
    k_pair<<<dim3(10, INNER_SLOTS), 256>>>();
    k_reduce<<<64, 256>>>(out);
}

// round 8
// speedup vs baseline: 3.1166x; 1.0415x over previous
#include <cuda_runtime.h>

#define NDOC  128
#define NIN   625
#define NLEAF 4096
#define CSC   16       // colsum row-chunks
#define GEMM_KB 12     // main gemm K-split
#define GKB     12     // G gemm K-split (3 tile-pairs x 12 = 36 blocks)
#define INNER_SLOTS 14 // inner pairwise K-slots (45 features each)

// ---------------- scratch (device globals; no allocation) ----------------
__device__ __align__(16) float g_cs[CSC][NLEAF];
__device__ __align__(16) float g_Wp[GEMM_KB][NIN * NDOC];        // split-K partials of W
__device__ __align__(16) float g_z[NIN * NDOC];                  // z, node-major [p][d]
__device__ __align__(16) float g_outp[INNER_SLOTS][NDOC * NDOC]; // inner pairwise partials
__device__ __align__(16) float g_Gp[GKB][NDOC * NDOC];           // mass@mass.T partials

__device__ __forceinline__ float tanh_apx(float x) {
    float y;
    asm("tanh.approx.f32 %0, %1;" : "=f"(y) : "f"(x));
    return y;
}

// -------- 1. partial column sums of exp(param) --------
__global__ __launch_bounds__(256) void k_colsum(const float* __restrict__ param) {
    int col = blockIdx.x * 256 + threadIdx.x;
    int rc  = blockIdx.y;
    int r0 = rc * 40;
    int r1 = min(r0 + 40, NIN);
    float s = 0.f;
    for (int r = r0; r < r1; r++)
        s += __expf(param[r * NLEAF + col]);
    g_cs[rc][col] = s;
}

// -------- 2. fused big wave: W-gemm (blocks 0..239) + G-gemm (blocks 240..275) --------
__constant__ int c_gbi[3] = {0, 0, 1};
__constant__ int c_gbj[3] = {0, 1, 1};

__global__ __launch_bounds__(256, 2) void k_big(const float* __restrict__ mass,
                                                const float* __restrict__ param) {
    __shared__ __align__(16) float sbuf[5728];
    int bx = blockIdx.x;
    int t = threadIdx.x;

    if (bx < 240) {
        // ===== W = (mass * rs) @ exp(param).T =====
        float* sA  = sbuf;               // [32][132]
        float* sB  = sbuf + 4224;        // [32][36]
        float* srs = sbuf + 4224 + 1152; // up to 352 cols
        int j0 = (bx % 20) * 32;
        int kb = bx / 20;
        int t0 = kb * 10 + min(kb, 8);
        int nt = 10 + (kb < 8 ? 1 : 0);
        int l0 = t0 * 32;
        int ncol = nt * 32;
        int lane = t & 31;
        int jg = t >> 5;

        for (int c = t; c < ncol; c += 256) {
            float s = 0.f;
#pragma unroll
            for (int y = 0; y < CSC; y++) s += g_cs[y][l0 + c];
            srs[c] = 1.0f / s;
        }
        __syncthreads();

        float acc[4][4];
#pragma unroll
        for (int r = 0; r < 4; r++)
#pragma unroll
            for (int c = 0; c < 4; c++) acc[r][c] = 0.f;

        for (int kt = 0; kt < nt; kt++) {
            int lb = (t0 + kt) * 32;
#pragma unroll
            for (int i = 0; i < 16; i++) {
                int idx = t + i * 256;
                int kk = idx & 31, d = idx >> 5;
                sA[kk * 132 + d] = mass[d * NLEAF + lb + kk] * srs[kt * 32 + kk];
            }
#pragma unroll
            for (int i = 0; i < 4; i++) {
                int idx = t + i * 256;
                int kk = idx & 31, jj = idx >> 5;
                int j = j0 + jj;
                sB[kk * 36 + jj] = (j < NIN) ? __expf(param[j * NLEAF + lb + kk]) : 0.f;
            }
            __syncthreads();
#pragma unroll
            for (int k = 0; k < 32; k++) {
                float4 a = *(const float4*)&sA[k * 132 + 4 * lane];
                float4 b = *(const float4*)&sB[k * 36 + jg * 4];
                acc[0][0] += a.x * b.x; acc[0][1] += a.x * b.y; acc[0][2] += a.x * b.z; acc[0][3] += a.x * b.w;
                acc[1][0] += a.y * b.x; acc[1][1] += a.y * b.y; acc[1][2] += a.y * b.z; acc[1][3] += a.y * b.w;
                acc[2][0] += a.z * b.x; acc[2][1] += a.z * b.y; acc[2][2] += a.z * b.z; acc[2][3] += a.z * b.w;
                acc[3][0] += a.w * b.x; acc[3][1] += a.w * b.y; acc[3][2] += a.w * b.z; acc[3][3] += a.w * b.w;
            }
            __syncthreads();
        }
#pragma unroll
        for (int c = 0; c < 4; c++) {
            int j = j0 + jg * 4 + c;
            if (j < NIN)
                *(float4*)&g_Wp[kb][j * NDOC + 4 * lane] =
                    make_float4(acc[0][c], acc[1][c], acc[2][c], acc[3][c]);
        }
    } else {
        // ===== G = mass @ mass.T, 64x64 tiles, 16x16 threads of 4x4 =====
        float* sI = sbuf;               // [32][68]
        float* sJ = sbuf + 2176;        // [32][68]
        int g  = bx - 240;
        int gt = g % 3;
        int kb = g / 3;
        int i0 = c_gbi[gt] * 64, j0 = c_gbj[gt] * 64;
        bool offdiag = (i0 != j0);
        int t0 = kb * 10 + min(kb, 8);
        int nt = 10 + (kb < 8 ? 1 : 0);
        int iq = t >> 4, jq = t & 15;

        float acc[4][4];
#pragma unroll
        for (int r = 0; r < 4; r++)
#pragma unroll
            for (int c = 0; c < 4; c++) acc[r][c] = 0.f;

        for (int kt = 0; kt < nt; kt++) {
            int lb = (t0 + kt) * 32;
#pragma unroll
            for (int i = 0; i < 8; i++) {
                int idx = t + i * 256;
                int kk = idx & 31, ii = idx >> 5;
                sI[kk * 68 + ii] = mass[(i0 + ii) * NLEAF + lb + kk];
                sJ[kk * 68 + ii] = mass[(j0 + ii) * NLEAF + lb + kk];
            }
            __syncthreads();
#pragma unroll
            for (int k = 0; k < 32; k++) {
                float4 a = *(const float4*)&sI[k * 68 + iq * 4];
                float4 b = *(const float4*)&sJ[k * 68 + jq * 4];
                acc[0][0] += a.x * b.x; acc[0][1] += a.x * b.y; acc[0][2] += a.x * b.z; acc[0][3] += a.x * b.w;
                acc[1][0] += a.y * b.x; acc[1][1] += a.y * b.y; acc[1][2] += a.y * b.z; acc[1][3] += a.y * b.w;
                acc[2][0] += a.z * b.x; acc[2][1] += a.z * b.y; acc[2][2] += a.z * b.z; acc[2][3] += a.z * b.w;
                acc[3][0] += a.w * b.x; acc[3][1] += a.w * b.y; acc[3][2] += a.w * b.z; acc[3][3] += a.w * b.w;
            }
            __syncthreads();
        }
        float* op = g_Gp[kb];
#pragma unroll
        for (int r = 0; r < 4; r++) {
            int i = i0 + iq * 4 + r;
            *(float4*)&op[i * NDOC + j0 + jq * 4] =
                make_float4(acc[r][0], acc[r][1], acc[r][2], acc[r][3]);
        }
        if (offdiag) {
#pragma unroll
            for (int r = 0; r < 4; r++)
#pragma unroll
                for (int c = 0; c < 4; c++)
                    op[(j0 + jq * 4 + c) * NDOC + i0 + iq * 4 + r] = acc[r][c];
        }
    }
}

// -------- 3. combine split-K partials + tree phase 1 fused --------
// After this kernel: g_z holds SUBTREE sums for nodes 31..624, plain W for 0..30.
__global__ __launch_bounds__(256) void k_combine() {
    int idx = blockIdx.x * 256 + threadIdx.x;
    if (idx < NIN * NDOC) {
        int n = idx >> 7, d = idx & 127;
        float s = 0.f;
#pragma unroll
        for (int kb = 0; kb < GEMM_KB; kb++) s += g_Wp[kb][idx];
        if (n >= 31 && n <= 124) {
            int c0 = 5 * n + 1;
            int c1 = min(c0 + 5, NIN);
            for (int c = c0; c < c1; c++) {
                int cidx = c * NDOC + d;
#pragma unroll
                for (int kb = 0; kb < GEMM_KB; kb++) s += g_Wp[kb][cidx];
            }
        }
        g_z[idx] = s;
    }
}

// -------- 4. inner pairwise x*tanh(x): 512-thread blocks, 14 slots of 45 --------
// Slot 0 blocks compute subtree sums for nodes 0..30 locally (uzI/uzJ) and use
// that buffer for their first k-tile (features 0..31).
__constant__ int c_tpi[10] = {0,0,0,0,1,1,1,2,2,3};
__constant__ int c_tpj[10] = {0,1,2,3,1,2,3,2,3,3};

__global__ __launch_bounds__(512) void k_pair() {
    __shared__ float sI[32 * 33];
    __shared__ float sJ[32 * 33];
    __shared__ float uzI[32 * 33];   // rows 0..30: local subtree sums; row 31: z[31]
    __shared__ float uzJ[32 * 33];
    int tp = blockIdx.x, s = blockIdx.y;
    int bi = c_tpi[tp], bj = c_tpj[tp];
    int i0 = bi * 32, j0 = bj * 32;
    int t = threadIdx.x;
    int tj  = t & 31;     // j-doc lane
    int tig = t >> 5;     // 0..15; i-docs = {tig, tig+16}

    if (s == 0) {
        // phase A: parents 6..30 (children 31..155 complete in g_z) + row 31 copy
        for (int it = t; it < 25 * 64 + 64; it += 512) {
            if (it < 25 * 64) {
                int p = 6 + (it >> 6), dd = it & 63;
                int doc = (dd < 32) ? i0 + dd : j0 + (dd - 32);
                float sv = g_z[p * NDOC + doc];
                int c0 = 5 * p + 1;
#pragma unroll
                for (int c = 0; c < 5; c++) sv += g_z[(c0 + c) * NDOC + doc];
                float* dst = (dd < 32) ? uzI : uzJ;
                dst[p * 33 + (dd & 31)] = sv;
            } else {
                int dd = it - 25 * 64;
                int doc = (dd < 32) ? i0 + dd : j0 + (dd - 32);
                float* dst = (dd < 32) ? uzI : uzJ;
                dst[31 * 33 + (dd & 31)] = g_z[31 * NDOC + doc];
            }
        }
        __syncthreads();
        // phase B: parents 1..5 (children 6..30 in uz)
        if (t < 5 * 64) {
            int p = 1 + (t >> 6), dd = t & 63;
            int doc = (dd < 32) ? i0 + dd : j0 + (dd - 32);
            float* buf = (dd < 32) ? uzI : uzJ;
            float sv = g_z[p * NDOC + doc];
            int c0 = 5 * p + 1;
#pragma unroll
            for (int c = 0; c < 5; c++) sv += buf[(c0 + c) * 33 + (dd & 31)];
            buf[p * 33 + (dd & 31)] = sv;
        }
        __syncthreads();
        // phase C: root (children 1..5 in uz)
        if (t < 64) {
            int dd = t;
            int doc = (dd < 32) ? i0 + dd : j0 + (dd - 32);
            float* buf = (dd < 32) ? uzI : uzJ;
            float sv = g_z[doc];
#pragma unroll
            for (int c = 1; c <= 5; c++) sv += buf[c * 33 + (dd & 31)];
            buf[(dd & 31)] = sv;
        }
        __syncthreads();
    }

    int k0 = s * 45;
    int k1 = min(k0 + 45, NIN);

    float acc0 = 0.f, acc1 = 0.f;

    for (int kt = k0; kt < k1; kt += 32) {
        const float* pI;
        const float* pJ;
        if (s == 0 && kt == 0) {
            pI = uzI; pJ = uzJ;        // nodes 0..31 already staged
        } else {
#pragma unroll
            for (int i = 0; i < 2; i++) {
                int idx = t + i * 512;            // 0..1023
                int ii = idx & 31, kk = idx >> 5;
                int kg = kt + kk;
                float vI = (kg < k1) ? g_z[kg * NDOC + i0 + ii] : 0.f;
                float vJ = (kg < k1) ? g_z[kg * NDOC + j0 + ii] : 0.f;
                sI[kk * 33 + ii] = vI;
                sJ[kk * 33 + ii] = vJ;
            }
            __syncthreads();
            pI = sI; pJ = sJ;
        }
#pragma unroll
        for (int k = 0; k < 32; k++) {
            float b  = pJ[k * 33 + tj];
            float d0 = pI[k * 33 + tig]      - b;
            float d1 = pI[k * 33 + tig + 16] - b;
            acc0 += d0 * tanh_apx(d0);
            acc1 += d1 * tanh_apx(d1);
        }
        __syncthreads();
    }

    float* op = g_outp[s];
    int j = j0 + tj;
    int i;
    i = i0 + tig;      op[i * NDOC + j] = acc0; if (bi != bj) op[j * NDOC + i] = acc0;
    i = i0 + tig + 16; op[i * NDOC + j] = acc1; if (bi != bj) op[j * NDOC + i] = acc1;
}

// -------- 5. final reduce: out = inner + (G_ii + G_jj - 2*G_ij); exact 0 diagonal --------
__global__ __launch_bounds__(256) void k_reduce(float* __restrict__ out) {
    int idx = blockIdx.x * 256 + threadIdx.x;   // 64*256 = 16384 exact
    int i = idx >> 7, j = idx & 127;
    float gg = 0.f, ni = 0.f, nj = 0.f;
#pragma unroll
    for (int kb = 0; kb < GKB; kb++) {
        gg += g_Gp[kb][idx];
        ni += g_Gp[kb][i * (NDOC + 1)];
        nj += g_Gp[kb][j * (NDOC + 1)];
    }
    float s = ni + nj - 2.0f * gg;              // d_leaf (quadratic smoothabs)
#pragma unroll
    for (int t = 0; t < INNER_SLOTS; t++) s += g_outp[t][idx];
    out[idx] = (i == j) ? 0.f : s;
}

// ---------------- launch ----------------
extern "C" void kernel_launch(void* const* d_in, const int* in_sizes, int n_in,
                              void* d_out, int out_size) {
    const float* mass  = (const float*)d_in[0];   // (128, 4096)
    const float* param = (const float*)d_in[1];   // (625, 4096)
    if (n_in >= 2 && in_sizes[0] == NIN * NLEAF && in_sizes[1] == NDOC * NLEAF) {
        param = (const float*)d_in[0];
        mass  = (const float*)d_in[1];
    }
    float* out = (float*)d_out;

    k_colsum<<<dim3(16, CSC), 256>>>(param);
    k_big<<<240 + 3 * GKB, 256>>>(mass, param);
    k_combine<<<(NIN * NDOC + 255) / 256, 256>>>();
    k_pair<<<dim3(10, INNER_SLOTS), 512>>>();
    k_reduce<<<64, 256>>>(out);
}